// round 14
// baseline (speedup 1.0000x reference)
#include <cuda_runtime.h>
#include <math.h>
#include <stdint.h>

// Problem constants
#define T_LEN 2048
#define C_DIM 1024
#define H_NUM 16
#define KVH_NUM 4
#define D_DIM 64
#define KV_DIM 256
#define LOG2E 1.4426950408889634f
#define SCALE2 (0.125f * LOG2E)
#define NEG_BIG -1e30f

// Scratch
__device__ float g_q[T_LEN * C_DIM];
__device__ float g_k[T_LEN * KV_DIM];
__device__ float g_v[T_LEN * KV_DIM];
__device__ float g_y[T_LEN * C_DIM];
__device__ float g_logf[H_NUM * T_LEN];
__device__ float g_c[H_NUM * T_LEN];
__device__ float g_po[2 * T_LEN * C_DIM];
__device__ float2 g_pml[2 * H_NUM * T_LEN];

// ---------------------------------------------------------------------------
// helpers
// ---------------------------------------------------------------------------
__device__ __forceinline__ uint32_t tf32r(float x) {
    uint32_t u;
    asm("cvt.rna.tf32.f32 %0, %1;" : "=r"(u) : "f"(x));
    return u;
}
__device__ __forceinline__ float fex2(float x) {
    float r;
    asm("ex2.approx.ftz.f32 %0, %1;" : "=f"(r) : "f"(x));
    return r;
}
__device__ __forceinline__ void mma_tf32(float* c, const uint32_t* a,
                                         uint32_t b0, uint32_t b1) {
    asm volatile(
        "mma.sync.aligned.m16n8k8.row.col.f32.tf32.tf32.f32 "
        "{%0,%1,%2,%3}, {%4,%5,%6,%7}, {%8,%9}, {%0,%1,%2,%3};"
        : "+f"(c[0]), "+f"(c[1]), "+f"(c[2]), "+f"(c[3])
        : "r"(a[0]), "r"(a[1]), "r"(a[2]), "r"(a[3]), "r"(b0), "r"(b1));
}
__device__ __forceinline__ void cp16(uint32_t dst, const void* src) {
    asm volatile("cp.async.cg.shared.global [%0], [%1], 16;"
                 :: "r"(dst), "l"(src));
}
__device__ __forceinline__ void cp4(uint32_t dst, const void* src) {
    asm volatile("cp.async.ca.shared.global [%0], [%1], 4;"
                 :: "r"(dst), "l"(src));
}
__device__ __forceinline__ uint32_t s2u(const void* p) {
    return (uint32_t)__cvta_generic_to_shared(p);
}

// ---------------------------------------------------------------------------
// Pipelined GEMM (R13, unchanged): 4-stage cp.async, tf32 round post-LDS.
// ---------------------------------------------------------------------------
#define GSTR 20
#define NSTG 4
#define STG_F ((128 + 64) * GSTR)
#define GEMM_SMEM (NSTG * STG_F * 4)

__global__ __launch_bounds__(256, 2)
void gemm_pipe_kernel(const float* __restrict__ A,
                      const float* __restrict__ Wq, float* __restrict__ Oq,
                      const float* __restrict__ Wk, float* __restrict__ Ok,
                      const float* __restrict__ Wv, float* __restrict__ Ov,
                      int K, int fused) {
    extern __shared__ float dsm[];

    const int bx = blockIdx.x;
    const float* W;
    float* O;
    int n0, Nout;
    if (fused && bx >= 16) {
        if (bx < 20) { W = Wk; O = Ok; n0 = (bx - 16) << 6; }
        else         { W = Wv; O = Ov; n0 = (bx - 20) << 6; }
        Nout = KV_DIM;
    } else {
        W = Wq; O = Oq; n0 = bx << 6; Nout = C_DIM;
    }
    const int m0 = blockIdx.y << 7;
    const int tid = threadIdx.x, wid = tid >> 5, lane = tid & 31;
    const int grp = lane >> 2, tg = lane & 3;
    const int wm = (wid & 3) << 5, wn = (wid >> 2) << 5;
    const int ar = tid >> 2, ac = (tid & 3) << 2;

    const float* Abase = A + (size_t)(m0 + ar) * K + ac;
    const float* Wbase = W + (size_t)(n0 + ar) * K + ac;

    const int NK = K >> 4;

    auto issue = [&](int ks) {
        float* As = dsm + (ks & (NSTG - 1)) * STG_F;
        float* Ws = As + 128 * GSTR;
        const float* ap = Abase + ks * 16;
        cp16(s2u(As + ar * GSTR + ac), ap);
        cp16(s2u(As + (ar + 64) * GSTR + ac), ap + (size_t)64 * K);
        cp16(s2u(Ws + ar * GSTR + ac), Wbase + ks * 16);
        asm volatile("cp.async.commit_group;");
    };

#pragma unroll
    for (int ks = 0; ks < NSTG - 1; ks++)
        if (ks < NK) issue(ks);

    float acc[2][4][4] = {};

    for (int ks = 0; ks < NK; ks++) {
        if (ks + NSTG - 1 < NK)
            asm volatile("cp.async.wait_group %0;" :: "n"(NSTG - 2));
        else
            asm volatile("cp.async.wait_group 0;");
        __syncthreads();
        if (ks + NSTG - 1 < NK) issue(ks + NSTG - 1);

        const float* As = dsm + (ks & (NSTG - 1)) * STG_F;
        const float* Ws = As + 128 * GSTR;

#pragma unroll
        for (int kb = 0; kb < 16; kb += 8) {
            uint32_t af[2][4];
#pragma unroll
            for (int mt = 0; mt < 2; mt++) {
                int mr = wm + (mt << 4);
                af[mt][0] = tf32r(As[(mr + grp) * GSTR + kb + tg]);
                af[mt][1] = tf32r(As[(mr + 8 + grp) * GSTR + kb + tg]);
                af[mt][2] = tf32r(As[(mr + grp) * GSTR + kb + tg + 4]);
                af[mt][3] = tf32r(As[(mr + 8 + grp) * GSTR + kb + tg + 4]);
            }
#pragma unroll
            for (int nt = 0; nt < 4; nt++) {
                int nc = wn + (nt << 3);
                uint32_t b0 = tf32r(Ws[(nc + grp) * GSTR + kb + tg]);
                uint32_t b1 = tf32r(Ws[(nc + grp) * GSTR + kb + tg + 4]);
                mma_tf32(acc[0][nt], af[0], b0, b1);
                mma_tf32(acc[1][nt], af[1], b0, b1);
            }
        }
    }
#pragma unroll
    for (int mt = 0; mt < 2; mt++)
#pragma unroll
        for (int nt = 0; nt < 4; nt++) {
            int row = m0 + wm + (mt << 4) + grp;
            int col = n0 + wn + (nt << 3) + (tg << 1);
            *(float2*)&O[(size_t)row * Nout + col] =
                make_float2(acc[mt][nt][0], acc[mt][nt][1]);
            *(float2*)&O[(size_t)(row + 8) * Nout + col] =
                make_float2(acc[mt][nt][2], acc[mt][nt][3]);
        }
}

// ---------------------------------------------------------------------------
// RMSNorm + RoPE (k tf32-rounded), v tf32-rounded, blocks 0..15 do cumsum.
// ---------------------------------------------------------------------------
__global__ void normrope_kernel(float* __restrict__ q, float* __restrict__ k,
                                float* __restrict__ v,
                                const float* __restrict__ qw,
                                const float* __restrict__ kw,
                                const float* __restrict__ lf,
                                float* __restrict__ cgout) {
    const int t = blockIdx.x;
    const int tid = threadIdx.x;
    __shared__ float buf[C_DIM];
    __shared__ float cs[32], sn[32];
    __shared__ float red[8];
    __shared__ float s_inv;

    if (tid < 32) {
        float th = (float)t * fex2((float)tid * -0.41524101186092029f);
        cs[tid] = cosf(th);
        sn[tid] = sinf(th);
    }

    float ss = 0.f;
    for (int c = tid; c < C_DIM; c += 256) {
        float vv = q[(size_t)t * C_DIM + c];
        buf[c] = vv;
        ss += vv * vv;
    }
#pragma unroll
    for (int o = 16; o; o >>= 1) ss += __shfl_xor_sync(0xffffffffu, ss, o);
    if ((tid & 31) == 0) red[tid >> 5] = ss;
    __syncthreads();
    if (tid == 0) {
        float tot = 0.f;
#pragma unroll
        for (int w = 0; w < 8; w++) tot += red[w];
        s_inv = rsqrtf(tot / (float)C_DIM + 1e-6f);
    }
    __syncthreads();
    float inv = s_inv;
    for (int c = tid; c < C_DIM; c += 256) {
        int d = c & 63;
        int f = d & 31;
        float xn = buf[c] * inv * qw[c];
        float other = (d < 32) ? -buf[c + 32] * inv * qw[c + 32]
                               :  buf[c - 32] * inv * qw[c - 32];
        q[(size_t)t * C_DIM + c] = xn * cs[f] + other * sn[f];
    }
    __syncthreads();

    float ss2 = 0.f;
    if (tid < KV_DIM) {
        float vv = k[(size_t)t * KV_DIM + tid];
        buf[tid] = vv;
        ss2 = vv * vv;
    }
#pragma unroll
    for (int o = 16; o; o >>= 1) ss2 += __shfl_xor_sync(0xffffffffu, ss2, o);
    if ((tid & 31) == 0) red[tid >> 5] = ss2;
    __syncthreads();
    if (tid == 0) {
        float tot = 0.f;
#pragma unroll
        for (int w = 0; w < 8; w++) tot += red[w];
        s_inv = rsqrtf(tot / (float)KV_DIM + 1e-6f);
    }
    __syncthreads();
    inv = s_inv;
    if (tid < KV_DIM) {
        int c = tid;
        int d = c & 63;
        int f = d & 31;
        float xn = buf[c] * inv * kw[c];
        float other = (d < 32) ? -buf[c + 32] * inv * kw[c + 32]
                               :  buf[c - 32] * inv * kw[c - 32];
        k[(size_t)t * KV_DIM + c] =
            __uint_as_float(tf32r(xn * cs[f] + other * sn[f]));
        v[(size_t)t * KV_DIM + c] =
            __uint_as_float(tf32r(v[(size_t)t * KV_DIM + c]));
    }

    if (blockIdx.x < 16 && tid < 32) {
        const int h = blockIdx.x;
        const int lane = tid;
        const float* src = lf + (size_t)h * T_LEN;
        float* dst = cgout + (size_t)h * T_LEN;
        const int base = lane * 64;
        float s = 0.f;
#pragma unroll 8
        for (int i = 0; i < 64; i++) s += src[base + i];
        float incl = s;
#pragma unroll
        for (int o = 1; o < 32; o <<= 1) {
            float vv = __shfl_up_sync(0xffffffffu, incl, o);
            if (lane >= o) incl += vv;
        }
        float run = incl - s;
#pragma unroll 8
        for (int i = 0; i < 64; i++) {
            run += src[base + i];
            dst[base + i] = run * LOG2E;
        }
    }
}

// ---------------------------------------------------------------------------
// Forgetting gate (unchanged).
// ---------------------------------------------------------------------------
__global__ __launch_bounds__(256, 2)
void gate_kernel(const float* __restrict__ x,
                 const float* __restrict__ wl,
                 const float* __restrict__ fg,
                 const float* __restrict__ fb,
                 float* __restrict__ logf_out) {
    __shared__ float xs[8][C_DIM];
    const int t0 = blockIdx.x << 3;
    const int tid = threadIdx.x;
    for (int i = tid; i < 8 * C_DIM; i += 256)
        xs[i >> 10][i & 1023] = x[(size_t)t0 * C_DIM + i];
    __syncthreads();

    const int h = tid >> 4, l16 = tid & 15;
    float z1[8] = {}, z2[8] = {};
    for (int c = l16; c < C_DIM; c += 16) {
        float wlv = wl[(size_t)c * H_NUM + h];
        float fgv = fg[(size_t)h * C_DIM + c];
#pragma unroll
        for (int g = 0; g < 8; g++) {
            float xv = xs[g][c];
            z1[g] += xv * wlv;
            z2[g] += xv * fgv;
        }
    }
#pragma unroll
    for (int o = 8; o; o >>= 1) {
#pragma unroll
        for (int g = 0; g < 8; g++) {
            z1[g] += __shfl_xor_sync(0xffffffffu, z1[g], o);
            z2[g] += __shfl_xor_sync(0xffffffffu, z2[g], o);
        }
    }
    if (l16 == 0) {
        float fbv = fb[h];
#pragma unroll
        for (int g = 0; g < 8; g++) {
            float lam = (z1[g] > 0.f ? z1[g] : expf(z1[g]) - 1.f) + 1.f;
            float logit = (z2[g] + fbv) * lam;
            float ls = (logit >= 0.f) ? -log1pf(expf(-logit))
                                      : (logit - log1pf(expf(logit)));
            logf_out[(size_t)h * T_LEN + t0 + g] = ls / (lam + 1e-3f);
        }
    }
}

// ---------------------------------------------------------------------------
// Flash attention SPLIT-K partials — PING-PONG version.
// Block = (q-tile, kvh, seg), 256 threads = 2 independent groups of 4 warps.
// Group g owns q-heads {2g, 2g+1} of this kvh, its own single-buffered K/V
// tile, and its own named barrier (id g+1) — groups never sync with each
// other, so their LDS/MUFU/MMA phases interleave across the SM.
// Per-(head,row) math identical to R13 -> bit-identical partials.
// Dynamic smem: 2 groups x (K+V tile 64x68) = 69632 B.
// ---------------------------------------------------------------------------
#define AP 68
#define TILE_F (2 * 64 * AP)   // floats per group buffer (K+V)

__global__ __launch_bounds__(256, 2)
void attn_part_kernel(const float* __restrict__ q, const float* __restrict__ k,
                      const float* __restrict__ v, const float* __restrict__ cg,
                      float* __restrict__ po, float2* __restrict__ pml) {
    extern __shared__ float dsm[];
    __shared__ float cjs_s[2][2][64];   // [group][local head][key]

    const int kvh = blockIdx.y >> 1;
    const int seg = blockIdx.y & 1;
    const int qt = 63 - blockIdx.x;
    const int i0 = qt << 5;
    const int tid = threadIdx.x;
    const int g = tid >> 7;             // group 0/1
    const int ltid = tid & 127;
    const int lwid = ltid >> 5;         // warp in group, 0..3
    const int lane = tid & 31;
    const int grp = lane >> 2, tg = lane & 3;
    const int hl = (g << 1) + (lwid >> 1);          // local head 0..3
    const int qh = (kvh << 2) + hl;
    const int r0 = i0 + ((lwid & 1) << 4) + grp;
    const int r1 = r0 + 8;

    const int ntiles = ((i0 + 31) >> 6) + 1;
    const int half = (ntiles + 1) >> 1;
    const int tb = seg ? half : 0;
    const int te = seg ? ntiles : half;

    float* poseg = po + (size_t)seg * T_LEN * C_DIM;
    float2* pmlseg = pml + (size_t)seg * H_NUM * T_LEN;

    if (tb >= te) {
        if (tid < 128) {
            int hh = tid >> 5, tt = i0 + (tid & 31);
            pmlseg[(size_t)((kvh << 2) + hh) * T_LEN + tt] =
                make_float2(NEG_BIG, 0.f);
        }
        return;
    }

    float* Ks = dsm + g * TILE_F;
    float* Vs = Ks + 64 * AP;

    // group loader: 128 threads, 8 K + 8 V cp16 each, 1 cjs cp4
    const int lr = ltid >> 4, lc4 = (ltid & 15) << 2;
    const int ch = ltid >> 6, ct = ltid & 63;
    auto issue_tile = [&](int jt) {
        const int j0 = jt << 6;
#pragma unroll
        for (int t = 0; t < 8; t++) {
            int r = lr + (t << 3);
            cp16(s2u(Ks + r * AP + lc4),
                 k + (size_t)(j0 + r) * KV_DIM + kvh * 64 + lc4);
            cp16(s2u(Vs + r * AP + lc4),
                 v + (size_t)(j0 + r) * KV_DIM + kvh * 64 + lc4);
        }
        cp4(s2u(&cjs_s[g][ch][ct]),
            cg + (size_t)((kvh << 2) + (g << 1) + ch) * T_LEN + j0 + ct);
        asm volatile("cp.async.commit_group;");
    };
    auto barg = [&]() {
        asm volatile("bar.sync %0, 128;" :: "r"(g + 1) : "memory");
    };

    uint32_t qa[8][4];
#pragma unroll
    for (int kt = 0; kt < 8; kt++) {
        const float* q0 = q + (size_t)r0 * C_DIM + qh * 64 + (kt << 3);
        const float* q1 = q + (size_t)r1 * C_DIM + qh * 64 + (kt << 3);
        qa[kt][0] = tf32r(q0[tg]);
        qa[kt][1] = tf32r(q1[tg]);
        qa[kt][2] = tf32r(q0[tg + 4]);
        qa[kt][3] = tf32r(q1[tg + 4]);
    }
    const float ci0 = cg[qh * T_LEN + r0], ci1 = cg[qh * T_LEN + r1];

    float m0 = NEG_BIG, m1 = NEG_BIG, l0 = 0.f, l1 = 0.f;
    float o[8][4] = {};

    const int hidx = lwid >> 1;   // 0/1: which of the group's 2 cjs rows

    for (int jt = tb; jt < te; jt++) {
        const int j0 = jt << 6;
        barg();                 // previous tile's readers done with buffer
        issue_tile(jt);
        asm volatile("cp.async.wait_group 0;");
        barg();                 // loads visible to whole group

        // S = Q K^T
        float s[8][4] = {};
#pragma unroll
        for (int kt = 0; kt < 8; kt++) {
#pragma unroll
            for (int nt = 0; nt < 8; nt++) {
                const float* kr = Ks + ((nt << 3) + grp) * AP + (kt << 3);
                uint32_t b0 = __float_as_uint(kr[tg]);
                uint32_t b1 = __float_as_uint(kr[tg + 4]);
                mma_tf32(s[nt], qa[kt], b0, b1);
            }
        }

        const bool diag = (jt == ntiles - 1);
        float mt0 = NEG_BIG, mt1 = NEG_BIG;
#pragma unroll
        for (int nt = 0; nt < 8; nt++) {
            int c0 = (nt << 3) + (tg << 1), c1 = c0 + 1;
            float b0v = cjs_s[g][hidx][c0], b1v = cjs_s[g][hidx][c1];
            s[nt][0] = s[nt][0] * SCALE2 + ci0 - b0v;
            s[nt][1] = s[nt][1] * SCALE2 + ci0 - b1v;
            s[nt][2] = s[nt][2] * SCALE2 + ci1 - b0v;
            s[nt][3] = s[nt][3] * SCALE2 + ci1 - b1v;
            if (diag) {
                if (j0 + c0 > r0) s[nt][0] = NEG_BIG;
                if (j0 + c1 > r0) s[nt][1] = NEG_BIG;
                if (j0 + c0 > r1) s[nt][2] = NEG_BIG;
                if (j0 + c1 > r1) s[nt][3] = NEG_BIG;
            }
            mt0 = fmaxf(mt0, fmaxf(s[nt][0], s[nt][1]));
            mt1 = fmaxf(mt1, fmaxf(s[nt][2], s[nt][3]));
        }
        mt0 = fmaxf(mt0, __shfl_xor_sync(0xffffffffu, mt0, 1));
        mt0 = fmaxf(mt0, __shfl_xor_sync(0xffffffffu, mt0, 2));
        mt1 = fmaxf(mt1, __shfl_xor_sync(0xffffffffu, mt1, 1));
        mt1 = fmaxf(mt1, __shfl_xor_sync(0xffffffffu, mt1, 2));

        float mn0 = fmaxf(m0, mt0), mn1 = fmaxf(m1, mt1);
        float al0 = fex2(m0 - mn0), al1 = fex2(m1 - mn1);
        float ps0 = 0.f, ps1 = 0.f;
#pragma unroll
        for (int nt = 0; nt < 8; nt++) {
            s[nt][0] = fex2(s[nt][0] - mn0);
            s[nt][1] = fex2(s[nt][1] - mn0);
            s[nt][2] = fex2(s[nt][2] - mn1);
            s[nt][3] = fex2(s[nt][3] - mn1);
            ps0 += s[nt][0] + s[nt][1];
            ps1 += s[nt][2] + s[nt][3];
        }
        ps0 += __shfl_xor_sync(0xffffffffu, ps0, 1);
        ps0 += __shfl_xor_sync(0xffffffffu, ps0, 2);
        ps1 += __shfl_xor_sync(0xffffffffu, ps1, 1);
        ps1 += __shfl_xor_sync(0xffffffffu, ps1, 2);
        l0 = l0 * al0 + ps0;
        l1 = l1 * al1 + ps1;
        m0 = mn0; m1 = mn1;
#pragma unroll
        for (int nt = 0; nt < 8; nt++) {
            o[nt][0] *= al0; o[nt][1] *= al0;
            o[nt][2] *= al1; o[nt][3] *= al1;
            s[nt][0] = __uint_as_float(tf32r(s[nt][0]));
            s[nt][1] = __uint_as_float(tf32r(s[nt][1]));
            s[nt][2] = __uint_as_float(tf32r(s[nt][2]));
            s[nt][3] = __uint_as_float(tf32r(s[nt][3]));
        }

        // O += P V (shuffle-built A frags)
        const int srcA = (grp << 2) + (tg >> 1);
        const int srcB = srcA + 2;
        const bool odd = (tg & 1);
#pragma unroll
        for (int kt = 0; kt < 8; kt++) {
            float x0 = __shfl_sync(0xffffffffu, s[kt][0], srcA);
            float x1 = __shfl_sync(0xffffffffu, s[kt][1], srcA);
            float x2 = __shfl_sync(0xffffffffu, s[kt][2], srcA);
            float x3 = __shfl_sync(0xffffffffu, s[kt][3], srcA);
            float y0 = __shfl_sync(0xffffffffu, s[kt][0], srcB);
            float y1 = __shfl_sync(0xffffffffu, s[kt][1], srcB);
            float y2 = __shfl_sync(0xffffffffu, s[kt][2], srcB);
            float y3 = __shfl_sync(0xffffffffu, s[kt][3], srcB);
            uint32_t pa[4];
            pa[0] = __float_as_uint(odd ? x1 : x0);
            pa[1] = __float_as_uint(odd ? x3 : x2);
            pa[2] = __float_as_uint(odd ? y1 : y0);
            pa[3] = __float_as_uint(odd ? y3 : y2);
#pragma unroll
            for (int nt = 0; nt < 8; nt++) {
                const float* vr = Vs + ((kt << 3) + tg) * AP + (nt << 3) + grp;
                uint32_t b0 = __float_as_uint(vr[0]);
                uint32_t b1 = __float_as_uint(vr[4 * AP]);
                mma_tf32(o[nt], pa, b0, b1);
            }
        }
    }

#pragma unroll
    for (int nt = 0; nt < 8; nt++) {
        int col = qh * 64 + (nt << 3) + (tg << 1);
        *(float2*)&poseg[(size_t)r0 * C_DIM + col] =
            make_float2(o[nt][0], o[nt][1]);
        *(float2*)&poseg[(size_t)r1 * C_DIM + col] =
            make_float2(o[nt][2], o[nt][3]);
    }
    if (tg == 0) {
        pmlseg[(size_t)qh * T_LEN + r0] = make_float2(m0, l0);
        pmlseg[(size_t)qh * T_LEN + r1] = make_float2(m1, l1);
    }
}

// ---------------------------------------------------------------------------
// Split-K merge -> y
// ---------------------------------------------------------------------------
__global__ __launch_bounds__(256)
void attn_merge_kernel(const float* __restrict__ po,
                       const float2* __restrict__ pml,
                       float* __restrict__ y) {
    const int t = blockIdx.x;
    const int c0 = threadIdx.x << 2;
    const int h = c0 >> 6;
    float2 ml0 = pml[(size_t)h * T_LEN + t];
    float2 ml1 = pml[(size_t)H_NUM * T_LEN + (size_t)h * T_LEN + t];
    float mm = fmaxf(ml0.x, ml1.x);
    float a0 = fex2(ml0.x - mm), a1 = fex2(ml1.x - mm);
    float inv = 1.f / (ml0.y * a0 + ml1.y * a1);
    float4 o0 = *(const float4*)(po + (size_t)t * C_DIM + c0);
    float4 o1 = *(const float4*)(po + (size_t)T_LEN * C_DIM + (size_t)t * C_DIM + c0);
    float4 r;
    r.x = (o0.x * a0 + o1.x * a1) * inv;
    r.y = (o0.y * a0 + o1.y * a1) * inv;
    r.z = (o0.z * a0 + o1.z * a1) * inv;
    r.w = (o0.w * a0 + o1.w * a1) * inv;
    *(float4*)(y + (size_t)t * C_DIM + c0) = r;
}

// ---------------------------------------------------------------------------
// kernel_launch — 0 gate, 1 qkv gemm, 2 normrope, 3 attn (PROFILED),
// 4 merge, 5 out gemm
// ---------------------------------------------------------------------------
extern "C" void kernel_launch(void* const* d_in, const int* in_sizes, int n_in,
                              void* d_out, int out_size) {
    const float* x  = (const float*)d_in[0];
    const float* Wq = (const float*)d_in[1];
    const float* Wk = (const float*)d_in[2];
    const float* Wv = (const float*)d_in[3];
    const float* Wo = (const float*)d_in[4];
    const float* qw = (const float*)d_in[5];
    const float* kw = (const float*)d_in[6];
    const float* fg = (const float*)d_in[7];
    const float* fb = (const float*)d_in[8];
    const float* wl = (const float*)d_in[9];
    float* out = (float*)d_out;

    float *qp, *kp, *vp, *yp, *lfp, *cp, *pop;
    float2* pmlp;
    cudaGetSymbolAddress((void**)&qp, g_q);
    cudaGetSymbolAddress((void**)&kp, g_k);
    cudaGetSymbolAddress((void**)&vp, g_v);
    cudaGetSymbolAddress((void**)&yp, g_y);
    cudaGetSymbolAddress((void**)&lfp, g_logf);
    cudaGetSymbolAddress((void**)&cp, g_c);
    cudaGetSymbolAddress((void**)&pop, g_po);
    cudaGetSymbolAddress((void**)&pmlp, g_pml);

    const int attn_smem = 2 * TILE_F * (int)sizeof(float);   // 69632 B
    cudaFuncSetAttribute(attn_part_kernel,
                         cudaFuncAttributeMaxDynamicSharedMemorySize, attn_smem);
    cudaFuncSetAttribute(gemm_pipe_kernel,
                         cudaFuncAttributeMaxDynamicSharedMemorySize, GEMM_SMEM);

    // 0: gate
    gate_kernel<<<T_LEN / 8, 256>>>(x, wl, fg, fb, lfp);
    // 1: fused Q/K/V projection (4-stage pipeline)
    gemm_pipe_kernel<<<dim3(24, T_LEN / 128), 256, GEMM_SMEM>>>(
        x, Wq, qp, Wk, kp, Wv, vp, C_DIM, 1);
    // 2: RMSNorm + RoPE (+ k/v tf32 rounding) + per-head cumsum
    normrope_kernel<<<T_LEN, 256>>>(qp, kp, vp, qw, kw, lfp, cp);
    // 3: flash attention split-K partials, ping-pong groups (PROFILED)
    attn_part_kernel<<<dim3(64, KVH_NUM * 2), 256, attn_smem>>>(
        qp, kp, vp, cp, pop, pmlp);
    // 4: split-K merge -> y
    attn_merge_kernel<<<T_LEN, 256>>>(pop, pmlp, yp);
    // 5: output projection (4-stage pipeline)
    gemm_pipe_kernel<<<dim3(16, T_LEN / 128), 256, GEMM_SMEM>>>(
        yp, Wo, out, Wo, out, Wo, out, C_DIM, 0);
}

// round 15
// speedup vs baseline: 1.0524x; 1.0524x over previous
#include <cuda_runtime.h>
#include <math.h>
#include <stdint.h>

// Problem constants
#define T_LEN 2048
#define C_DIM 1024
#define H_NUM 16
#define KVH_NUM 4
#define D_DIM 64
#define KV_DIM 256
#define LOG2E 1.4426950408889634f
#define SCALE2 (0.125f * LOG2E)
#define NEG_BIG -1e30f
#define NSEG 4

// Scratch
__device__ float g_q[T_LEN * C_DIM];
__device__ float g_k[T_LEN * KV_DIM];
__device__ float g_v[T_LEN * KV_DIM];
__device__ float g_y[T_LEN * C_DIM];
__device__ float g_logf[H_NUM * T_LEN];
__device__ float g_c[H_NUM * T_LEN];
__device__ float g_po[NSEG * T_LEN * C_DIM];
__device__ float2 g_pml[NSEG * H_NUM * T_LEN];

// ---------------------------------------------------------------------------
// helpers
// ---------------------------------------------------------------------------
__device__ __forceinline__ uint32_t tf32r(float x) {
    uint32_t u;
    asm("cvt.rna.tf32.f32 %0, %1;" : "=r"(u) : "f"(x));
    return u;
}
__device__ __forceinline__ float fex2(float x) {
    float r;
    asm("ex2.approx.ftz.f32 %0, %1;" : "=f"(r) : "f"(x));
    return r;
}
__device__ __forceinline__ void mma_tf32(float* c, const uint32_t* a,
                                         uint32_t b0, uint32_t b1) {
    asm volatile(
        "mma.sync.aligned.m16n8k8.row.col.f32.tf32.tf32.f32 "
        "{%0,%1,%2,%3}, {%4,%5,%6,%7}, {%8,%9}, {%0,%1,%2,%3};"
        : "+f"(c[0]), "+f"(c[1]), "+f"(c[2]), "+f"(c[3])
        : "r"(a[0]), "r"(a[1]), "r"(a[2]), "r"(a[3]), "r"(b0), "r"(b1));
}
__device__ __forceinline__ void cp16(uint32_t dst, const void* src) {
    asm volatile("cp.async.cg.shared.global [%0], [%1], 16;"
                 :: "r"(dst), "l"(src));
}
__device__ __forceinline__ void cp4(uint32_t dst, const void* src) {
    asm volatile("cp.async.ca.shared.global [%0], [%1], 4;"
                 :: "r"(dst), "l"(src));
}
__device__ __forceinline__ uint32_t s2u(const void* p) {
    return (uint32_t)__cvta_generic_to_shared(p);
}

// ---------------------------------------------------------------------------
// Pipelined GEMM (R13, unchanged): 4-stage cp.async, tf32 round post-LDS.
// ---------------------------------------------------------------------------
#define GSTR 20
#define NSTG 4
#define STG_F ((128 + 64) * GSTR)
#define GEMM_SMEM (NSTG * STG_F * 4)

__global__ __launch_bounds__(256, 2)
void gemm_pipe_kernel(const float* __restrict__ A,
                      const float* __restrict__ Wq, float* __restrict__ Oq,
                      const float* __restrict__ Wk, float* __restrict__ Ok,
                      const float* __restrict__ Wv, float* __restrict__ Ov,
                      int K, int fused) {
    extern __shared__ float dsm[];

    const int bx = blockIdx.x;
    const float* W;
    float* O;
    int n0, Nout;
    if (fused && bx >= 16) {
        if (bx < 20) { W = Wk; O = Ok; n0 = (bx - 16) << 6; }
        else         { W = Wv; O = Ov; n0 = (bx - 20) << 6; }
        Nout = KV_DIM;
    } else {
        W = Wq; O = Oq; n0 = bx << 6; Nout = C_DIM;
    }
    const int m0 = blockIdx.y << 7;
    const int tid = threadIdx.x, wid = tid >> 5, lane = tid & 31;
    const int grp = lane >> 2, tg = lane & 3;
    const int wm = (wid & 3) << 5, wn = (wid >> 2) << 5;
    const int ar = tid >> 2, ac = (tid & 3) << 2;

    const float* Abase = A + (size_t)(m0 + ar) * K + ac;
    const float* Wbase = W + (size_t)(n0 + ar) * K + ac;

    const int NK = K >> 4;

    auto issue = [&](int ks) {
        float* As = dsm + (ks & (NSTG - 1)) * STG_F;
        float* Ws = As + 128 * GSTR;
        const float* ap = Abase + ks * 16;
        cp16(s2u(As + ar * GSTR + ac), ap);
        cp16(s2u(As + (ar + 64) * GSTR + ac), ap + (size_t)64 * K);
        cp16(s2u(Ws + ar * GSTR + ac), Wbase + ks * 16);
        asm volatile("cp.async.commit_group;");
    };

#pragma unroll
    for (int ks = 0; ks < NSTG - 1; ks++)
        if (ks < NK) issue(ks);

    float acc[2][4][4] = {};

    for (int ks = 0; ks < NK; ks++) {
        if (ks + NSTG - 1 < NK)
            asm volatile("cp.async.wait_group %0;" :: "n"(NSTG - 2));
        else
            asm volatile("cp.async.wait_group 0;");
        __syncthreads();
        if (ks + NSTG - 1 < NK) issue(ks + NSTG - 1);

        const float* As = dsm + (ks & (NSTG - 1)) * STG_F;
        const float* Ws = As + 128 * GSTR;

#pragma unroll
        for (int kb = 0; kb < 16; kb += 8) {
            uint32_t af[2][4];
#pragma unroll
            for (int mt = 0; mt < 2; mt++) {
                int mr = wm + (mt << 4);
                af[mt][0] = tf32r(As[(mr + grp) * GSTR + kb + tg]);
                af[mt][1] = tf32r(As[(mr + 8 + grp) * GSTR + kb + tg]);
                af[mt][2] = tf32r(As[(mr + grp) * GSTR + kb + tg + 4]);
                af[mt][3] = tf32r(As[(mr + 8 + grp) * GSTR + kb + tg + 4]);
            }
#pragma unroll
            for (int nt = 0; nt < 4; nt++) {
                int nc = wn + (nt << 3);
                uint32_t b0 = tf32r(Ws[(nc + grp) * GSTR + kb + tg]);
                uint32_t b1 = tf32r(Ws[(nc + grp) * GSTR + kb + tg + 4]);
                mma_tf32(acc[0][nt], af[0], b0, b1);
                mma_tf32(acc[1][nt], af[1], b0, b1);
            }
        }
    }
#pragma unroll
    for (int mt = 0; mt < 2; mt++)
#pragma unroll
        for (int nt = 0; nt < 4; nt++) {
            int row = m0 + wm + (mt << 4) + grp;
            int col = n0 + wn + (nt << 3) + (tg << 1);
            *(float2*)&O[(size_t)row * Nout + col] =
                make_float2(acc[mt][nt][0], acc[mt][nt][1]);
            *(float2*)&O[(size_t)(row + 8) * Nout + col] =
                make_float2(acc[mt][nt][2], acc[mt][nt][3]);
        }
}

// ---------------------------------------------------------------------------
// RMSNorm + RoPE (k tf32-rounded), v tf32-rounded, blocks 0..15 do cumsum.
// ---------------------------------------------------------------------------
__global__ void normrope_kernel(float* __restrict__ q, float* __restrict__ k,
                                float* __restrict__ v,
                                const float* __restrict__ qw,
                                const float* __restrict__ kw,
                                const float* __restrict__ lf,
                                float* __restrict__ cgout) {
    const int t = blockIdx.x;
    const int tid = threadIdx.x;
    __shared__ float buf[C_DIM];
    __shared__ float cs[32], sn[32];
    __shared__ float red[8];
    __shared__ float s_inv;

    if (tid < 32) {
        float th = (float)t * fex2((float)tid * -0.41524101186092029f);
        cs[tid] = cosf(th);
        sn[tid] = sinf(th);
    }

    float ss = 0.f;
    for (int c = tid; c < C_DIM; c += 256) {
        float vv = q[(size_t)t * C_DIM + c];
        buf[c] = vv;
        ss += vv * vv;
    }
#pragma unroll
    for (int o = 16; o; o >>= 1) ss += __shfl_xor_sync(0xffffffffu, ss, o);
    if ((tid & 31) == 0) red[tid >> 5] = ss;
    __syncthreads();
    if (tid == 0) {
        float tot = 0.f;
#pragma unroll
        for (int w = 0; w < 8; w++) tot += red[w];
        s_inv = rsqrtf(tot / (float)C_DIM + 1e-6f);
    }
    __syncthreads();
    float inv = s_inv;
    for (int c = tid; c < C_DIM; c += 256) {
        int d = c & 63;
        int f = d & 31;
        float xn = buf[c] * inv * qw[c];
        float other = (d < 32) ? -buf[c + 32] * inv * qw[c + 32]
                               :  buf[c - 32] * inv * qw[c - 32];
        q[(size_t)t * C_DIM + c] = xn * cs[f] + other * sn[f];
    }
    __syncthreads();

    float ss2 = 0.f;
    if (tid < KV_DIM) {
        float vv = k[(size_t)t * KV_DIM + tid];
        buf[tid] = vv;
        ss2 = vv * vv;
    }
#pragma unroll
    for (int o = 16; o; o >>= 1) ss2 += __shfl_xor_sync(0xffffffffu, ss2, o);
    if ((tid & 31) == 0) red[tid >> 5] = ss2;
    __syncthreads();
    if (tid == 0) {
        float tot = 0.f;
#pragma unroll
        for (int w = 0; w < 8; w++) tot += red[w];
        s_inv = rsqrtf(tot / (float)KV_DIM + 1e-6f);
    }
    __syncthreads();
    inv = s_inv;
    if (tid < KV_DIM) {
        int c = tid;
        int d = c & 63;
        int f = d & 31;
        float xn = buf[c] * inv * kw[c];
        float other = (d < 32) ? -buf[c + 32] * inv * kw[c + 32]
                               :  buf[c - 32] * inv * kw[c - 32];
        k[(size_t)t * KV_DIM + c] =
            __uint_as_float(tf32r(xn * cs[f] + other * sn[f]));
        v[(size_t)t * KV_DIM + c] =
            __uint_as_float(tf32r(v[(size_t)t * KV_DIM + c]));
    }

    if (blockIdx.x < 16 && tid < 32) {
        const int h = blockIdx.x;
        const int lane = tid;
        const float* src = lf + (size_t)h * T_LEN;
        float* dst = cgout + (size_t)h * T_LEN;
        const int base = lane * 64;
        float s = 0.f;
#pragma unroll 8
        for (int i = 0; i < 64; i++) s += src[base + i];
        float incl = s;
#pragma unroll
        for (int o = 1; o < 32; o <<= 1) {
            float vv = __shfl_up_sync(0xffffffffu, incl, o);
            if (lane >= o) incl += vv;
        }
        float run = incl - s;
#pragma unroll 8
        for (int i = 0; i < 64; i++) {
            run += src[base + i];
            dst[base + i] = run * LOG2E;
        }
    }
}

// ---------------------------------------------------------------------------
// Forgetting gate (unchanged).
// ---------------------------------------------------------------------------
__global__ __launch_bounds__(256, 2)
void gate_kernel(const float* __restrict__ x,
                 const float* __restrict__ wl,
                 const float* __restrict__ fg,
                 const float* __restrict__ fb,
                 float* __restrict__ logf_out) {
    __shared__ float xs[8][C_DIM];
    const int t0 = blockIdx.x << 3;
    const int tid = threadIdx.x;
    for (int i = tid; i < 8 * C_DIM; i += 256)
        xs[i >> 10][i & 1023] = x[(size_t)t0 * C_DIM + i];
    __syncthreads();

    const int h = tid >> 4, l16 = tid & 15;
    float z1[8] = {}, z2[8] = {};
    for (int c = l16; c < C_DIM; c += 16) {
        float wlv = wl[(size_t)c * H_NUM + h];
        float fgv = fg[(size_t)h * C_DIM + c];
#pragma unroll
        for (int g = 0; g < 8; g++) {
            float xv = xs[g][c];
            z1[g] += xv * wlv;
            z2[g] += xv * fgv;
        }
    }
#pragma unroll
    for (int o = 8; o; o >>= 1) {
#pragma unroll
        for (int g = 0; g < 8; g++) {
            z1[g] += __shfl_xor_sync(0xffffffffu, z1[g], o);
            z2[g] += __shfl_xor_sync(0xffffffffu, z2[g], o);
        }
    }
    if (l16 == 0) {
        float fbv = fb[h];
#pragma unroll
        for (int g = 0; g < 8; g++) {
            float lam = (z1[g] > 0.f ? z1[g] : expf(z1[g]) - 1.f) + 1.f;
            float logit = (z2[g] + fbv) * lam;
            float ls = (logit >= 0.f) ? -log1pf(expf(-logit))
                                      : (logit - log1pf(expf(logit)));
            logf_out[(size_t)h * T_LEN + t0 + g] = ls / (lam + 1e-3f);
        }
    }
}

// ---------------------------------------------------------------------------
// Flash attention 4-WAY SPLIT-K partials (R13 body, seg in blockIdx.y&3).
// grid = (64, KVH*4) = 1024 blocks; max block ~9 tiles.
// ---------------------------------------------------------------------------
#define AP 68
#define STAGE_F (2 * 64 * AP)
__shared__ float cjs_s[2][4][64];

__global__ __launch_bounds__(256, 2)
void attn_part_kernel(const float* __restrict__ q, const float* __restrict__ k,
                      const float* __restrict__ v, const float* __restrict__ cg,
                      float* __restrict__ po, float2* __restrict__ pml) {
    extern __shared__ float dsm[];

    const int kvh = blockIdx.y >> 2;
    const int seg = blockIdx.y & 3;
    const int qt = 63 - blockIdx.x;
    const int i0 = qt << 5;
    const int tid = threadIdx.x, wid = tid >> 5, lane = tid & 31;
    const int grp = lane >> 2, tg = lane & 3;
    const int hl = wid >> 1;
    const int qh = (kvh << 2) + hl;
    const int r0 = i0 + ((wid & 1) << 4) + grp;
    const int r1 = r0 + 8;

    const int ntiles = ((i0 + 31) >> 6) + 1;
    const int tb = (ntiles * seg) >> 2;
    const int te = (ntiles * (seg + 1)) >> 2;

    float* poseg = po + (size_t)seg * T_LEN * C_DIM;
    float2* pmlseg = pml + (size_t)seg * H_NUM * T_LEN;

    if (tb >= te) {   // empty segment: mark and exit
        if (tid < 128) {
            int hh = tid >> 5, tt = i0 + (tid & 31);
            pmlseg[(size_t)((kvh << 2) + hh) * T_LEN + tt] =
                make_float2(NEG_BIG, 0.f);
        }
        return;
    }

    const int lr = tid >> 4, lc4 = (tid & 15) << 2;
    const int ch = tid >> 6, ct = tid & 63;
    auto issue_tile = [&](int jt) {
        const int st = jt & 1;
        const int j0 = jt << 6;
        float* Ks = dsm + st * STAGE_F;
        float* Vs = Ks + 64 * AP;
#pragma unroll
        for (int t = 0; t < 4; t++) {
            int r = lr + (t << 4);
            cp16(s2u(Ks + r * AP + lc4),
                 k + (size_t)(j0 + r) * KV_DIM + kvh * 64 + lc4);
            cp16(s2u(Vs + r * AP + lc4),
                 v + (size_t)(j0 + r) * KV_DIM + kvh * 64 + lc4);
        }
        cp4(s2u(&cjs_s[st][ch][ct]),
            cg + (size_t)((kvh << 2) + ch) * T_LEN + j0 + ct);
        asm volatile("cp.async.commit_group;");
    };

    uint32_t qa[8][4];
#pragma unroll
    for (int kt = 0; kt < 8; kt++) {
        const float* q0 = q + (size_t)r0 * C_DIM + qh * 64 + (kt << 3);
        const float* q1 = q + (size_t)r1 * C_DIM + qh * 64 + (kt << 3);
        qa[kt][0] = tf32r(q0[tg]);
        qa[kt][1] = tf32r(q1[tg]);
        qa[kt][2] = tf32r(q0[tg + 4]);
        qa[kt][3] = tf32r(q1[tg + 4]);
    }
    const float ci0 = cg[qh * T_LEN + r0], ci1 = cg[qh * T_LEN + r1];

    float m0 = NEG_BIG, m1 = NEG_BIG, l0 = 0.f, l1 = 0.f;
    float o[8][4] = {};

    issue_tile(tb);

    for (int jt = tb; jt < te; jt++) {
        const int j0 = jt << 6;
        const int st = jt & 1;
        asm volatile("cp.async.wait_group 0;");
        __syncthreads();
        if (jt + 1 < te) issue_tile(jt + 1);

        const float* Ks = dsm + st * STAGE_F;
        const float* Vs = Ks + 64 * AP;

        float s[8][4] = {};
#pragma unroll
        for (int kt = 0; kt < 8; kt++) {
#pragma unroll
            for (int nt = 0; nt < 8; nt++) {
                const float* kr = Ks + ((nt << 3) + grp) * AP + (kt << 3);
                uint32_t b0 = __float_as_uint(kr[tg]);
                uint32_t b1 = __float_as_uint(kr[tg + 4]);
                mma_tf32(s[nt], qa[kt], b0, b1);
            }
        }

        const bool diag = (jt == ntiles - 1);
        float mt0 = NEG_BIG, mt1 = NEG_BIG;
#pragma unroll
        for (int nt = 0; nt < 8; nt++) {
            int c0 = (nt << 3) + (tg << 1), c1 = c0 + 1;
            float b0v = cjs_s[st][hl][c0], b1v = cjs_s[st][hl][c1];
            s[nt][0] = s[nt][0] * SCALE2 + ci0 - b0v;
            s[nt][1] = s[nt][1] * SCALE2 + ci0 - b1v;
            s[nt][2] = s[nt][2] * SCALE2 + ci1 - b0v;
            s[nt][3] = s[nt][3] * SCALE2 + ci1 - b1v;
            if (diag) {
                if (j0 + c0 > r0) s[nt][0] = NEG_BIG;
                if (j0 + c1 > r0) s[nt][1] = NEG_BIG;
                if (j0 + c0 > r1) s[nt][2] = NEG_BIG;
                if (j0 + c1 > r1) s[nt][3] = NEG_BIG;
            }
            mt0 = fmaxf(mt0, fmaxf(s[nt][0], s[nt][1]));
            mt1 = fmaxf(mt1, fmaxf(s[nt][2], s[nt][3]));
        }
        mt0 = fmaxf(mt0, __shfl_xor_sync(0xffffffffu, mt0, 1));
        mt0 = fmaxf(mt0, __shfl_xor_sync(0xffffffffu, mt0, 2));
        mt1 = fmaxf(mt1, __shfl_xor_sync(0xffffffffu, mt1, 1));
        mt1 = fmaxf(mt1, __shfl_xor_sync(0xffffffffu, mt1, 2));

        float mn0 = fmaxf(m0, mt0), mn1 = fmaxf(m1, mt1);
        float al0 = fex2(m0 - mn0), al1 = fex2(m1 - mn1);
        float ps0 = 0.f, ps1 = 0.f;
#pragma unroll
        for (int nt = 0; nt < 8; nt++) {
            s[nt][0] = fex2(s[nt][0] - mn0);
            s[nt][1] = fex2(s[nt][1] - mn0);
            s[nt][2] = fex2(s[nt][2] - mn1);
            s[nt][3] = fex2(s[nt][3] - mn1);
            ps0 += s[nt][0] + s[nt][1];
            ps1 += s[nt][2] + s[nt][3];
        }
        ps0 += __shfl_xor_sync(0xffffffffu, ps0, 1);
        ps0 += __shfl_xor_sync(0xffffffffu, ps0, 2);
        ps1 += __shfl_xor_sync(0xffffffffu, ps1, 1);
        ps1 += __shfl_xor_sync(0xffffffffu, ps1, 2);
        l0 = l0 * al0 + ps0;
        l1 = l1 * al1 + ps1;
        m0 = mn0; m1 = mn1;
#pragma unroll
        for (int nt = 0; nt < 8; nt++) {
            o[nt][0] *= al0; o[nt][1] *= al0;
            o[nt][2] *= al1; o[nt][3] *= al1;
            s[nt][0] = __uint_as_float(tf32r(s[nt][0]));
            s[nt][1] = __uint_as_float(tf32r(s[nt][1]));
            s[nt][2] = __uint_as_float(tf32r(s[nt][2]));
            s[nt][3] = __uint_as_float(tf32r(s[nt][3]));
        }

        const int srcA = (grp << 2) + (tg >> 1);
        const int srcB = srcA + 2;
        const bool odd = (tg & 1);
#pragma unroll
        for (int kt = 0; kt < 8; kt++) {
            float x0 = __shfl_sync(0xffffffffu, s[kt][0], srcA);
            float x1 = __shfl_sync(0xffffffffu, s[kt][1], srcA);
            float x2 = __shfl_sync(0xffffffffu, s[kt][2], srcA);
            float x3 = __shfl_sync(0xffffffffu, s[kt][3], srcA);
            float y0 = __shfl_sync(0xffffffffu, s[kt][0], srcB);
            float y1 = __shfl_sync(0xffffffffu, s[kt][1], srcB);
            float y2 = __shfl_sync(0xffffffffu, s[kt][2], srcB);
            float y3 = __shfl_sync(0xffffffffu, s[kt][3], srcB);
            uint32_t pa[4];
            pa[0] = __float_as_uint(odd ? x1 : x0);
            pa[1] = __float_as_uint(odd ? x3 : x2);
            pa[2] = __float_as_uint(odd ? y1 : y0);
            pa[3] = __float_as_uint(odd ? y3 : y2);
#pragma unroll
            for (int nt = 0; nt < 8; nt++) {
                const float* vr = Vs + ((kt << 3) + tg) * AP + (nt << 3) + grp;
                uint32_t b0 = __float_as_uint(vr[0]);
                uint32_t b1 = __float_as_uint(vr[4 * AP]);
                mma_tf32(o[nt], pa, b0, b1);
            }
        }
    }

#pragma unroll
    for (int nt = 0; nt < 8; nt++) {
        int col = qh * 64 + (nt << 3) + (tg << 1);
        *(float2*)&poseg[(size_t)r0 * C_DIM + col] =
            make_float2(o[nt][0], o[nt][1]);
        *(float2*)&poseg[(size_t)r1 * C_DIM + col] =
            make_float2(o[nt][2], o[nt][3]);
    }
    if (tg == 0) {
        pmlseg[(size_t)qh * T_LEN + r0] = make_float2(m0, l0);
        pmlseg[(size_t)qh * T_LEN + r1] = make_float2(m1, l1);
    }
}

// ---------------------------------------------------------------------------
// Split-K merge (4 segments) -> y
// ---------------------------------------------------------------------------
__global__ __launch_bounds__(256)
void attn_merge_kernel(const float* __restrict__ po,
                       const float2* __restrict__ pml,
                       float* __restrict__ y) {
    const int t = blockIdx.x;
    const int c0 = threadIdx.x << 2;
    const int h = c0 >> 6;
    float2 ml[NSEG];
    float mm = NEG_BIG;
#pragma unroll
    for (int s = 0; s < NSEG; s++) {
        ml[s] = pml[(size_t)s * H_NUM * T_LEN + (size_t)h * T_LEN + t];
        mm = fmaxf(mm, ml[s].x);
    }
    float a[NSEG], lsum = 0.f;
#pragma unroll
    for (int s = 0; s < NSEG; s++) {
        a[s] = fex2(ml[s].x - mm);
        lsum += ml[s].y * a[s];
    }
    float inv = 1.f / lsum;
    float4 r = make_float4(0.f, 0.f, 0.f, 0.f);
#pragma unroll
    for (int s = 0; s < NSEG; s++) {
        float4 ov = *(const float4*)(po + (size_t)s * T_LEN * C_DIM +
                                     (size_t)t * C_DIM + c0);
        float w = a[s];
        r.x += ov.x * w; r.y += ov.y * w;
        r.z += ov.z * w; r.w += ov.w * w;
    }
    r.x *= inv; r.y *= inv; r.z *= inv; r.w *= inv;
    *(float4*)(y + (size_t)t * C_DIM + c0) = r;
}

// ---------------------------------------------------------------------------
// kernel_launch — 0 gate, 1 qkv gemm, 2 normrope, 3 attn (PROFILED),
// 4 merge, 5 out gemm
// ---------------------------------------------------------------------------
extern "C" void kernel_launch(void* const* d_in, const int* in_sizes, int n_in,
                              void* d_out, int out_size) {
    const float* x  = (const float*)d_in[0];
    const float* Wq = (const float*)d_in[1];
    const float* Wk = (const float*)d_in[2];
    const float* Wv = (const float*)d_in[3];
    const float* Wo = (const float*)d_in[4];
    const float* qw = (const float*)d_in[5];
    const float* kw = (const float*)d_in[6];
    const float* fg = (const float*)d_in[7];
    const float* fb = (const float*)d_in[8];
    const float* wl = (const float*)d_in[9];
    float* out = (float*)d_out;

    float *qp, *kp, *vp, *yp, *lfp, *cp, *pop;
    float2* pmlp;
    cudaGetSymbolAddress((void**)&qp, g_q);
    cudaGetSymbolAddress((void**)&kp, g_k);
    cudaGetSymbolAddress((void**)&vp, g_v);
    cudaGetSymbolAddress((void**)&yp, g_y);
    cudaGetSymbolAddress((void**)&lfp, g_logf);
    cudaGetSymbolAddress((void**)&cp, g_c);
    cudaGetSymbolAddress((void**)&pop, g_po);
    cudaGetSymbolAddress((void**)&pmlp, g_pml);

    const int attn_smem = 2 * STAGE_F * (int)sizeof(float);   // 69632 B
    cudaFuncSetAttribute(attn_part_kernel,
                         cudaFuncAttributeMaxDynamicSharedMemorySize, attn_smem);
    cudaFuncSetAttribute(gemm_pipe_kernel,
                         cudaFuncAttributeMaxDynamicSharedMemorySize, GEMM_SMEM);

    // 0: gate
    gate_kernel<<<T_LEN / 8, 256>>>(x, wl, fg, fb, lfp);
    // 1: fused Q/K/V projection (4-stage pipeline)
    gemm_pipe_kernel<<<dim3(24, T_LEN / 128), 256, GEMM_SMEM>>>(
        x, Wq, qp, Wk, kp, Wv, vp, C_DIM, 1);
    // 2: RMSNorm + RoPE (+ k/v tf32 rounding) + per-head cumsum
    normrope_kernel<<<T_LEN, 256>>>(qp, kp, vp, qw, kw, lfp, cp);
    // 3: flash attention 4-way split-K partials (PROFILED)
    attn_part_kernel<<<dim3(64, KVH_NUM * NSEG), 256, attn_smem>>>(
        qp, kp, vp, cp, pop, pmlp);
    // 4: split-K merge (4 segments) -> y
    attn_merge_kernel<<<T_LEN, 256>>>(pop, pmlp, yp);
    // 5: output projection (4-stage pipeline)
    gemm_pipe_kernel<<<dim3(16, T_LEN / 128), 256, GEMM_SMEM>>>(
        yp, Wo, out, Wo, out, Wo, out, C_DIM, 0);
}